// round 9
// baseline (speedup 1.0000x reference)
#include <cuda_runtime.h>

#define NN 100000
#define NE 3200000

// Scratch for per-node aggregation (allocation-free rule: __device__ global).
__device__ __align__(16) float g_aggr[(size_t)NN * 16];
// 1 if edge_index is int64, 0 if int32.
__device__ int g_idx64;

// Zero the aggregation buffer; block 0 also detects the index dtype.
__global__ void zero_detect_kernel(const long long* __restrict__ ei64) {
    int i = blockIdx.x * blockDim.x + threadIdx.x;
    if (i < NN * 4) ((float4*)g_aggr)[i] = make_float4(0.f, 0.f, 0.f, 0.f);
    if (blockIdx.x == 0) {
        __shared__ int bad;
        if (threadIdx.x == 0) bad = 0;
        __syncthreads();
        int b = 0;
        for (int k = threadIdx.x; k < 8192; k += blockDim.x) {
            long long v = ei64[k];
            if (v < 0 || v >= NN) b = 1;
        }
        if (b) bad = 1;
        __syncthreads();
        if (threadIdx.x == 0) g_idx64 = bad ? 0 : 1;
    }
}

// 4 threads per edge; thread owns 4 of the 16 channels.
// Quad-coalesced x gather (4 lanes read one 64B row) and quad-coalesced RED.v4.
__global__ void __launch_bounds__(256) edge_kernel(
        const float* __restrict__ x,
        const void* __restrict__ ei_raw,
        const float* __restrict__ ea,
        const float* __restrict__ w1,
        const float* __restrict__ b1) {
    __shared__ float sw[128];  // [16][8]
    __shared__ float sb[16];
    int t = threadIdx.x;
    if (t < 128) sw[t] = w1[t];
    if (t < 16)  sb[t] = b1[t];
    __syncthreads();

    long long gt = (long long)blockIdx.x * blockDim.x + t;
    long long e  = gt >> 2;      // edge id
    int cg = (int)(gt & 3);      // channel group: channels cg*4 .. cg*4+3
    if (e >= NE) return;

    long long s, d;
    if (g_idx64) {
        const long long* ei = (const long long*)ei_raw;
        s = __ldg(ei + e);
        d = __ldg(ei + NE + e);
    } else {
        const int* ei = (const int*)ei_raw;
        s = __ldg(ei + e);
        d = __ldg(ei + NE + e);
    }
    if (s < 0) s = 0; if (s >= NN) s = NN - 1;
    if (d < 0) d = 0; if (d >= NN) d = NN - 1;

    // Full ea row (quad lanes read same 32B -> dedup'd in L1 coalescer).
    const float4* eap = (const float4*)(ea + e * 8);
    float4 a0 = __ldg(eap);
    float4 a1 = __ldg(eap + 1);

    // 4 output channels for this thread.
    const float* w = sw + cg * 32;   // 4 rows x 8 weights
    float m0 = sb[cg * 4 + 0], m1 = sb[cg * 4 + 1];
    float m2 = sb[cg * 4 + 2], m3 = sb[cg * 4 + 3];
    m0 += w[0]*a0.x + w[1]*a0.y + w[2]*a0.z + w[3]*a0.w
        + w[4]*a1.x + w[5]*a1.y + w[6]*a1.z + w[7]*a1.w;
    w += 8;
    m1 += w[0]*a0.x + w[1]*a0.y + w[2]*a0.z + w[3]*a0.w
        + w[4]*a1.x + w[5]*a1.y + w[6]*a1.z + w[7]*a1.w;
    w += 8;
    m2 += w[0]*a0.x + w[1]*a0.y + w[2]*a0.z + w[3]*a0.w
        + w[4]*a1.x + w[5]*a1.y + w[6]*a1.z + w[7]*a1.w;
    w += 8;
    m3 += w[0]*a0.x + w[1]*a0.y + w[2]*a0.z + w[3]*a0.w
        + w[4]*a1.x + w[5]*a1.y + w[6]*a1.z + w[7]*a1.w;

    // Quad-coalesced gather of this thread's quarter of x[src].
    float4 xv = __ldg((const float4*)x + s * 4 + cg);
    float r0 = fmaxf(m0 + xv.x, 0.f);
    float r1 = fmaxf(m1 + xv.y, 0.f);
    float r2 = fmaxf(m2 + xv.z, 0.f);
    float r3 = fmaxf(m3 + xv.w, 0.f);

    float* dst = g_aggr + d * 16 + cg * 4;
    asm volatile("red.global.add.v4.f32 [%0], {%1,%2,%3,%4};"
                 :: "l"(dst), "f"(r0), "f"(r1), "f"(r2), "f"(r3)
                 : "memory");
}

// One thread per node: out[n] = W2 @ (x[n] + aggr[n]) + b2, vectorized LDS.
__global__ void node_kernel(const float* __restrict__ x,
                            const float* __restrict__ w2,
                            const float* __restrict__ b2,
                            float* __restrict__ out) {
    __shared__ float sw[512];  // [32][16]
    __shared__ float sb[32];
    int t = threadIdx.x;
    for (int i = t; i < 512; i += blockDim.x) sw[i] = w2[i];
    if (t < 32) sb[t] = b2[t];
    __syncthreads();

    int n = blockIdx.x * blockDim.x + t;
    if (n >= NN) return;

    float4 h[4];
    const float4* xp = (const float4*)(x + (size_t)n * 16);
    const float4* ap = (const float4*)(g_aggr + (size_t)n * 16);
#pragma unroll
    for (int q = 0; q < 4; q++) {
        float4 xv = __ldg(xp + q);
        float4 av = ap[q];
        h[q] = make_float4(xv.x + av.x, xv.y + av.y, xv.z + av.z, xv.w + av.w);
    }

    float4* op = (float4*)(out + (size_t)n * 32);
#pragma unroll
    for (int o = 0; o < 32; o += 4) {
        float acc[4];
#pragma unroll
        for (int j = 0; j < 4; j++) {
            const float4* w4 = (const float4*)(sw + (o + j) * 16);
            float s = sb[o + j];
#pragma unroll
            for (int q = 0; q < 4; q++) {
                float4 wv = w4[q];
                s += wv.x * h[q].x + wv.y * h[q].y + wv.z * h[q].z + wv.w * h[q].w;
            }
            acc[j] = s;
        }
        op[o / 4] = make_float4(acc[0], acc[1], acc[2], acc[3]);
    }
}

extern "C" void kernel_launch(void* const* d_in, const int* in_sizes, int n_in,
                              void* d_out, int out_size) {
    // metadata order: x, edge_index, edge_attr, lin1_w, lin1_b, nn_w, nn_b
    const float* x   = (const float*)d_in[0];
    const void*  ei  = d_in[1];
    const float* ea  = (const float*)d_in[2];
    const float* w1  = (const float*)d_in[3];
    const float* b1  = (const float*)d_in[4];
    const float* w2  = (const float*)d_in[5];
    const float* b2  = (const float*)d_in[6];
    float*       out = (float*)d_out;

    zero_detect_kernel<<<(NN * 4 + 255) / 256, 256>>>((const long long*)ei);
    // 4 threads per edge
    long long total = (long long)NE * 4;
    edge_kernel<<<(unsigned)((total + 255) / 256), 256>>>(x, ei, ea, w1, b1);
    node_kernel<<<(NN + 255) / 256, 256>>>(x, w2, b2, out);
}

// round 11
// speedup vs baseline: 1.9299x; 1.9299x over previous
#include <cuda_runtime.h>

#define NN 100000
#define NE 3200000

// Scratch for per-node aggregation (allocation-free rule: __device__ global).
__device__ __align__(16) float g_aggr[(size_t)NN * 16];
// 1 if edge_index is int64, 0 if int32.
__device__ int g_idx64;

// Zero the aggregation buffer (64B per thread); block 0 also detects index dtype.
__global__ void zero_detect_kernel(const long long* __restrict__ ei64) {
    int i = blockIdx.x * blockDim.x + threadIdx.x;
    float4* p = (float4*)g_aggr;
    int base = i * 4;
    float4 z = make_float4(0.f, 0.f, 0.f, 0.f);
#pragma unroll
    for (int k = 0; k < 4; k++)
        if (base + k < NN * 4) p[base + k] = z;
    if (blockIdx.x == 0) {
        __shared__ int bad;
        if (threadIdx.x == 0) bad = 0;
        __syncthreads();
        int b = 0;
        for (int k = threadIdx.x; k < 8192; k += blockDim.x) {
            long long v = ei64[k];
            if (v < 0 || v >= NN) b = 1;
        }
        if (b) bad = 1;
        __syncthreads();
        if (threadIdx.x == 0) g_idx64 = bad ? 0 : 1;
    }
}

// Grid-stride, 4 lanes per edge, weights in REGISTERS (no smem -> no bank
// conflicts, no per-edge weight loads). Lane's channel group cg = tid&3 is
// invariant because the stride is a multiple of 4.
__global__ void __launch_bounds__(256) edge_kernel(
        const float* __restrict__ x,
        const void* __restrict__ ei_raw,
        const float* __restrict__ ea,
        const float* __restrict__ w1,
        const float* __restrict__ b1) {
    const int t  = threadIdx.x;
    const int cg = t & 3;  // channels cg*4 .. cg*4+3

    // Per-thread weights: rows cg*4..cg*4+3 of W1 [16][8], loaded once.
    float wr[4][8];
    float br[4];
#pragma unroll
    for (int j = 0; j < 4; j++) {
        const float4* wp = (const float4*)(w1 + (cg * 4 + j) * 8);
        float4 wa = __ldg(wp);
        float4 wb = __ldg(wp + 1);
        wr[j][0] = wa.x; wr[j][1] = wa.y; wr[j][2] = wa.z; wr[j][3] = wa.w;
        wr[j][4] = wb.x; wr[j][5] = wb.y; wr[j][6] = wb.z; wr[j][7] = wb.w;
        br[j] = __ldg(b1 + cg * 4 + j);
    }
    const int idx64 = g_idx64;
    const long long total  = (long long)NE * 4;
    const long long stride = (long long)gridDim.x * blockDim.x;  // multiple of 4

    for (long long gt = (long long)blockIdx.x * blockDim.x + t; gt < total; gt += stride) {
        long long e = gt >> 2;

        long long s, d;
        if (idx64) {
            const long long* ei = (const long long*)ei_raw;
            s = __ldg(ei + e);
            d = __ldg(ei + NE + e);
        } else {
            const int* ei = (const int*)ei_raw;
            s = __ldg(ei + e);
            d = __ldg(ei + NE + e);
        }
        if (s < 0) s = 0; if (s >= NN) s = NN - 1;
        if (d < 0) d = 0; if (d >= NN) d = NN - 1;

        // Full ea row; quad lanes hit the same 32B (dedup'd in L1 coalescer).
        const float4* eap = (const float4*)(ea + e * 8);
        float4 a0 = __ldg(eap);
        float4 a1 = __ldg(eap + 1);
        float a[8] = {a0.x, a0.y, a0.z, a0.w, a1.x, a1.y, a1.z, a1.w};

        float m[4];
#pragma unroll
        for (int j = 0; j < 4; j++) {
            float acc = br[j];
#pragma unroll
            for (int k = 0; k < 8; k++) acc += wr[j][k] * a[k];
            m[j] = acc;
        }

        // Quad-coalesced gather of this lane's quarter of x[src] (one 64B row/quad).
        float4 xv = __ldg((const float4*)x + s * 4 + cg);
        float r0 = fmaxf(m[0] + xv.x, 0.f);
        float r1 = fmaxf(m[1] + xv.y, 0.f);
        float r2 = fmaxf(m[2] + xv.z, 0.f);
        float r3 = fmaxf(m[3] + xv.w, 0.f);

        // Quad-coalesced RED.v4 (one 64B line per quad).
        float* dst = g_aggr + d * 16 + cg * 4;
        asm volatile("red.global.add.v4.f32 [%0], {%1,%2,%3,%4};"
                     :: "l"(dst), "f"(r0), "f"(r1), "f"(r2), "f"(r3)
                     : "memory");
    }
}

// One thread per node: out[n] = W2 @ (x[n] + aggr[n]) + b2.
// Weight LDS.128 reads are warp-uniform (broadcast) -> conflict-free.
__global__ void node_kernel(const float* __restrict__ x,
                            const float* __restrict__ w2,
                            const float* __restrict__ b2,
                            float* __restrict__ out) {
    __shared__ float sw[512];  // [32][16]
    __shared__ float sb[32];
    int t = threadIdx.x;
    for (int i = t; i < 512; i += blockDim.x) sw[i] = w2[i];
    if (t < 32) sb[t] = b2[t];
    __syncthreads();

    int n = blockIdx.x * blockDim.x + t;
    if (n >= NN) return;

    float4 h[4];
    const float4* xp = (const float4*)(x + (size_t)n * 16);
    const float4* ap = (const float4*)(g_aggr + (size_t)n * 16);
#pragma unroll
    for (int q = 0; q < 4; q++) {
        float4 xv = __ldg(xp + q);
        float4 av = ap[q];
        h[q] = make_float4(xv.x + av.x, xv.y + av.y, xv.z + av.z, xv.w + av.w);
    }

    float4* op = (float4*)(out + (size_t)n * 32);
#pragma unroll
    for (int o = 0; o < 32; o += 4) {
        float acc[4];
#pragma unroll
        for (int j = 0; j < 4; j++) {
            const float4* w4 = (const float4*)(sw + (o + j) * 16);
            float s = sb[o + j];
#pragma unroll
            for (int q = 0; q < 4; q++) {
                float4 wv = w4[q];
                s += wv.x * h[q].x + wv.y * h[q].y + wv.z * h[q].z + wv.w * h[q].w;
            }
            acc[j] = s;
        }
        op[o / 4] = make_float4(acc[0], acc[1], acc[2], acc[3]);
    }
}

extern "C" void kernel_launch(void* const* d_in, const int* in_sizes, int n_in,
                              void* d_out, int out_size) {
    // metadata order: x, edge_index, edge_attr, lin1_w, lin1_b, nn_w, nn_b
    const float* x   = (const float*)d_in[0];
    const void*  ei  = d_in[1];
    const float* ea  = (const float*)d_in[2];
    const float* w1  = (const float*)d_in[3];
    const float* b1  = (const float*)d_in[4];
    const float* w2  = (const float*)d_in[5];
    const float* b2  = (const float*)d_in[6];
    float*       out = (float*)d_out;

    // 64B per thread -> 391 blocks
    zero_detect_kernel<<<(NN * 16 + 256 * 16 - 1) / (256 * 16), 256>>>((const long long*)ei);
    // Grid-stride edge kernel: 16 blocks per SM (148 SMs).
    edge_kernel<<<148 * 16, 256>>>(x, ei, ea, w1, b1);
    node_kernel<<<(NN + 255) / 256, 256>>>(x, w2, b2, out);
}

// round 12
// speedup vs baseline: 1.9617x; 1.0165x over previous
#include <cuda_runtime.h>

#define NN 100000
#define NE 3200000

// Scratch for per-node aggregation (allocation-free rule: __device__ global).
__device__ __align__(16) float g_aggr[(size_t)NN * 16];
// 1 if edge_index is int64, 0 if int32.
__device__ int g_idx64;

// Zero the aggregation buffer (one float4 per thread, max parallelism).
// Block 0 detects index dtype with ONE load per thread (parallel, ~1 DRAM RTT).
__global__ void zero_detect_kernel(const long long* __restrict__ ei64) {
    int i = blockIdx.x * blockDim.x + threadIdx.x;
    if (i < NN * 4) ((float4*)g_aggr)[i] = make_float4(0.f, 0.f, 0.f, 0.f);
    if (blockIdx.x == 0) {
        __shared__ int bad;
        if (threadIdx.x == 0) bad = 0;
        __syncthreads();
        // One sample per thread, strided across the first half of edge_index.
        // int32 data read as int64 = lo + hi*2^32; bad unless hi==0 (P=1e-5).
        long long v = ei64[(size_t)threadIdx.x * 4096];
        if (v < 0 || v >= NN) bad = 1;
        __syncthreads();
        if (threadIdx.x == 0) g_idx64 = bad ? 0 : 1;
    }
}

// Grid-stride, 4 lanes per edge, weights in REGISTERS (no smem -> no bank
// conflicts, no per-edge weight loads). Lane's channel group cg = tid&3 is
// invariant because the stride is a multiple of 4.
__global__ void __launch_bounds__(256) edge_kernel(
        const float* __restrict__ x,
        const void* __restrict__ ei_raw,
        const float* __restrict__ ea,
        const float* __restrict__ w1,
        const float* __restrict__ b1) {
    const int t  = threadIdx.x;
    const int cg = t & 3;  // channels cg*4 .. cg*4+3

    // Per-thread weights: rows cg*4..cg*4+3 of W1 [16][8], loaded once.
    float wr[4][8];
    float br[4];
#pragma unroll
    for (int j = 0; j < 4; j++) {
        const float4* wp = (const float4*)(w1 + (cg * 4 + j) * 8);
        float4 wa = __ldg(wp);
        float4 wb = __ldg(wp + 1);
        wr[j][0] = wa.x; wr[j][1] = wa.y; wr[j][2] = wa.z; wr[j][3] = wa.w;
        wr[j][4] = wb.x; wr[j][5] = wb.y; wr[j][6] = wb.z; wr[j][7] = wb.w;
        br[j] = __ldg(b1 + cg * 4 + j);
    }
    const int idx64 = g_idx64;
    const long long total  = (long long)NE * 4;
    const long long stride = (long long)gridDim.x * blockDim.x;  // multiple of 4

    for (long long gt = (long long)blockIdx.x * blockDim.x + t; gt < total; gt += stride) {
        long long e = gt >> 2;

        long long s, d;
        if (idx64) {
            const long long* ei = (const long long*)ei_raw;
            s = __ldg(ei + e);
            d = __ldg(ei + NE + e);
        } else {
            const int* ei = (const int*)ei_raw;
            s = __ldg(ei + e);
            d = __ldg(ei + NE + e);
        }
        if (s < 0) s = 0; if (s >= NN) s = NN - 1;
        if (d < 0) d = 0; if (d >= NN) d = NN - 1;

        // Full ea row; quad lanes hit the same 32B (dedup'd in L1 coalescer).
        const float4* eap = (const float4*)(ea + e * 8);
        float4 a0 = __ldg(eap);
        float4 a1 = __ldg(eap + 1);
        float a[8] = {a0.x, a0.y, a0.z, a0.w, a1.x, a1.y, a1.z, a1.w};

        float m[4];
#pragma unroll
        for (int j = 0; j < 4; j++) {
            float acc = br[j];
#pragma unroll
            for (int k = 0; k < 8; k++) acc += wr[j][k] * a[k];
            m[j] = acc;
        }

        // Quad-coalesced gather of this lane's quarter of x[src] (one 64B row/quad).
        float4 xv = __ldg((const float4*)x + s * 4 + cg);
        float r0 = fmaxf(m[0] + xv.x, 0.f);
        float r1 = fmaxf(m[1] + xv.y, 0.f);
        float r2 = fmaxf(m[2] + xv.z, 0.f);
        float r3 = fmaxf(m[3] + xv.w, 0.f);

        // Quad-coalesced RED.v4 (one 64B line per quad).
        float* dst = g_aggr + d * 16 + cg * 4;
        asm volatile("red.global.add.v4.f32 [%0], {%1,%2,%3,%4};"
                     :: "l"(dst), "f"(r0), "f"(r1), "f"(r2), "f"(r3)
                     : "memory");
    }
}

// One thread per node: out[n] = W2 @ (x[n] + aggr[n]) + b2.
// Weight LDS.128 reads are warp-uniform (broadcast) -> conflict-free.
__global__ void node_kernel(const float* __restrict__ x,
                            const float* __restrict__ w2,
                            const float* __restrict__ b2,
                            float* __restrict__ out) {
    __shared__ float sw[512];  // [32][16]
    __shared__ float sb[32];
    int t = threadIdx.x;
    for (int i = t; i < 512; i += blockDim.x) sw[i] = w2[i];
    if (t < 32) sb[t] = b2[t];
    __syncthreads();

    int n = blockIdx.x * blockDim.x + t;
    if (n >= NN) return;

    float4 h[4];
    const float4* xp = (const float4*)(x + (size_t)n * 16);
    const float4* ap = (const float4*)(g_aggr + (size_t)n * 16);
#pragma unroll
    for (int q = 0; q < 4; q++) {
        float4 xv = __ldg(xp + q);
        float4 av = ap[q];
        h[q] = make_float4(xv.x + av.x, xv.y + av.y, xv.z + av.z, xv.w + av.w);
    }

    float4* op = (float4*)(out + (size_t)n * 32);
#pragma unroll
    for (int o = 0; o < 32; o += 4) {
        float acc[4];
#pragma unroll
        for (int j = 0; j < 4; j++) {
            const float4* w4 = (const float4*)(sw + (o + j) * 16);
            float s = sb[o + j];
#pragma unroll
            for (int q = 0; q < 4; q++) {
                float4 wv = w4[q];
                s += wv.x * h[q].x + wv.y * h[q].y + wv.z * h[q].z + wv.w * h[q].w;
            }
            acc[j] = s;
        }
        op[o / 4] = make_float4(acc[0], acc[1], acc[2], acc[3]);
    }
}

extern "C" void kernel_launch(void* const* d_in, const int* in_sizes, int n_in,
                              void* d_out, int out_size) {
    // metadata order: x, edge_index, edge_attr, lin1_w, lin1_b, nn_w, nn_b
    const float* x   = (const float*)d_in[0];
    const void*  ei  = d_in[1];
    const float* ea  = (const float*)d_in[2];
    const float* w1  = (const float*)d_in[3];
    const float* b1  = (const float*)d_in[4];
    const float* w2  = (const float*)d_in[5];
    const float* b2  = (const float*)d_in[6];
    float*       out = (float*)d_out;

    zero_detect_kernel<<<(NN * 4 + 255) / 256, 256>>>((const long long*)ei);
    // Grid-stride edge kernel: 16 blocks per SM (148 SMs).
    edge_kernel<<<148 * 16, 256>>>(x, ei, ea, w1, b1);
    node_kernel<<<(NN + 255) / 256, 256>>>(x, w2, b2, out);
}

// round 16
// speedup vs baseline: 2.3331x; 1.1893x over previous
#include <cuda_runtime.h>

#define NN 100000
#define NE 3200000

// Scratch for per-node aggregation (allocation-free rule: __device__ global).
__device__ __align__(16) float g_aggr[(size_t)NN * 16];
// 1 if edge_index is int64, 0 if int32.
__device__ int g_idx64;

// Zero the aggregation buffer (one float4 per thread).
// Block 0 detects index dtype with ONE load per thread (parallel).
__global__ void zero_detect_kernel(const long long* __restrict__ ei64) {
    int i = blockIdx.x * blockDim.x + threadIdx.x;
    if (i < NN * 4) ((float4*)g_aggr)[i] = make_float4(0.f, 0.f, 0.f, 0.f);
    if (blockIdx.x == 0) {
        __shared__ int bad;
        if (threadIdx.x == 0) bad = 0;
        __syncthreads();
        // int32 data read as int64 = lo + hi*2^32; bad unless hi==0 (P=1e-5).
        long long v = ei64[(size_t)threadIdx.x * 4096];
        if (v < 0 || v >= NN) bad = 1;
        __syncthreads();
        if (threadIdx.x == 0) g_idx64 = bad ? 0 : 1;
    }
}

// Grid-stride, 4 lanes per edge, register weights, SOFTWARE-PIPELINED:
// next iteration's indices + edge_attr are prefetched while the current
// edge computes, so the idx->gather->RED chain never serializes.
__global__ void __launch_bounds__(256) edge_kernel(
        const float* __restrict__ x,
        const void* __restrict__ ei_raw,
        const float* __restrict__ ea,
        const float* __restrict__ w1,
        const float* __restrict__ b1) {
    const int t  = threadIdx.x;
    const int cg = t & 3;  // channels cg*4 .. cg*4+3

    // Per-thread weights: rows cg*4..cg*4+3 of W1 [16][8], loaded once.
    float wr[4][8];
    float br[4];
#pragma unroll
    for (int j = 0; j < 4; j++) {
        const float4* wp = (const float4*)(w1 + (cg * 4 + j) * 8);
        float4 wa = __ldg(wp);
        float4 wb = __ldg(wp + 1);
        wr[j][0] = wa.x; wr[j][1] = wa.y; wr[j][2] = wa.z; wr[j][3] = wa.w;
        wr[j][4] = wb.x; wr[j][5] = wb.y; wr[j][6] = wb.z; wr[j][7] = wb.w;
        br[j] = __ldg(b1 + cg * 4 + j);
    }
    const int idx64 = g_idx64;
    const long long total  = (long long)NE * 4;
    const long long stride = (long long)gridDim.x * blockDim.x;  // multiple of 4

    long long gt = (long long)blockIdx.x * blockDim.x + t;
    if (gt >= total) return;

    // Prologue: indices + ea for the first edge.
    long long e = gt >> 2;
    long long s, d;
    if (idx64) {
        const long long* ei = (const long long*)ei_raw;
        s = __ldg(ei + e); d = __ldg(ei + NE + e);
    } else {
        const int* ei = (const int*)ei_raw;
        s = __ldg(ei + e); d = __ldg(ei + NE + e);
    }
    if (s < 0) s = 0; if (s >= NN) s = NN - 1;
    if (d < 0) d = 0; if (d >= NN) d = NN - 1;
    const float4* eap = (const float4*)ea;
    float4 a0 = __ldg(eap + e * 2);
    float4 a1 = __ldg(eap + e * 2 + 1);

    while (true) {
        // Issue the x gather for the CURRENT edge immediately (index is ready).
        float4 xv = __ldg((const float4*)x + s * 4 + cg);
        long long d_cur = d;

        // Prefetch NEXT iteration's indices + ea (overlaps with compute below).
        long long gtn = gt + stride;
        bool has_next = gtn < total;
        long long en = has_next ? (gtn >> 2) : e;  // safe re-load if last
        long long sn, dn;
        if (idx64) {
            const long long* ei = (const long long*)ei_raw;
            sn = __ldg(ei + en); dn = __ldg(ei + NE + en);
        } else {
            const int* ei = (const int*)ei_raw;
            sn = __ldg(ei + en); dn = __ldg(ei + NE + en);
        }
        float4 a0n = __ldg(eap + en * 2);
        float4 a1n = __ldg(eap + en * 2 + 1);

        // Compute message for current edge (weights + ea in registers).
        float a[8] = {a0.x, a0.y, a0.z, a0.w, a1.x, a1.y, a1.z, a1.w};
        float m[4];
#pragma unroll
        for (int j = 0; j < 4; j++) {
            float acc = br[j];
#pragma unroll
            for (int k = 0; k < 8; k++) acc += wr[j][k] * a[k];
            m[j] = acc;
        }

        float r0 = fmaxf(m[0] + xv.x, 0.f);
        float r1 = fmaxf(m[1] + xv.y, 0.f);
        float r2 = fmaxf(m[2] + xv.z, 0.f);
        float r3 = fmaxf(m[3] + xv.w, 0.f);

        float* dst = g_aggr + d_cur * 16 + cg * 4;
        asm volatile("red.global.add.v4.f32 [%0], {%1,%2,%3,%4};"
                     :: "l"(dst), "f"(r0), "f"(r1), "f"(r2), "f"(r3)
                     : "memory");

        if (!has_next) break;
        gt = gtn; e = en;
        s = sn; d = dn;
        if (s < 0) s = 0; if (s >= NN) s = NN - 1;
        if (d < 0) d = 0; if (d >= NN) d = NN - 1;
        a0 = a0n; a1 = a1n;
    }
}

// One thread per node: out[n] = W2 @ (x[n] + aggr[n]) + b2.
// Weight LDS.128 reads are warp-uniform (broadcast) -> conflict-free.
__global__ void node_kernel(const float* __restrict__ x,
                            const float* __restrict__ w2,
                            const float* __restrict__ b2,
                            float* __restrict__ out) {
    __shared__ float sw[512];  // [32][16]
    __shared__ float sb[32];
    int t = threadIdx.x;
    for (int i = t; i < 512; i += blockDim.x) sw[i] = w2[i];
    if (t < 32) sb[t] = b2[t];
    __syncthreads();

    int n = blockIdx.x * blockDim.x + t;
    if (n >= NN) return;

    float4 h[4];
    const float4* xp = (const float4*)(x + (size_t)n * 16);
    const float4* ap = (const float4*)(g_aggr + (size_t)n * 16);
#pragma unroll
    for (int q = 0; q < 4; q++) {
        float4 xv = __ldg(xp + q);
        float4 av = ap[q];
        h[q] = make_float4(xv.x + av.x, xv.y + av.y, xv.z + av.z, xv.w + av.w);
    }

    float4* op = (float4*)(out + (size_t)n * 32);
#pragma unroll
    for (int o = 0; o < 32; o += 4) {
        float acc[4];
#pragma unroll
        for (int j = 0; j < 4; j++) {
            const float4* w4 = (const float4*)(sw + (o + j) * 16);
            float s = sb[o + j];
#pragma unroll
            for (int q = 0; q < 4; q++) {
                float4 wv = w4[q];
                s += wv.x * h[q].x + wv.y * h[q].y + wv.z * h[q].z + wv.w * h[q].w;
            }
            acc[j] = s;
        }
        op[o / 4] = make_float4(acc[0], acc[1], acc[2], acc[3]);
    }
}

extern "C" void kernel_launch(void* const* d_in, const int* in_sizes, int n_in,
                              void* d_out, int out_size) {
    // metadata order: x, edge_index, edge_attr, lin1_w, lin1_b, nn_w, nn_b
    const float* x   = (const float*)d_in[0];
    const void*  ei  = d_in[1];
    const float* ea  = (const float*)d_in[2];
    const float* w1  = (const float*)d_in[3];
    const float* b1  = (const float*)d_in[4];
    const float* w2  = (const float*)d_in[5];
    const float* b2  = (const float*)d_in[6];
    float*       out = (float*)d_out;

    zero_detect_kernel<<<(NN * 4 + 255) / 256, 256>>>((const long long*)ei);
    // Grid-stride edge kernel: 16 blocks per SM (148 SMs).
    edge_kernel<<<148 * 16, 256>>>(x, ei, ea, w1, b1);
    node_kernel<<<(NN + 255) / 256, 256>>>(x, w2, b2, out);
}